// round 1
// baseline (speedup 1.0000x reference)
#include <cuda_runtime.h>
#include <cuda_bf16.h>
#include <cstdint>

// Problem constants (fixed by the reference setup_inputs):
//   flows:  [B=4, L=32, 2,  H=128, W=128] fp32
//   images: [B=4, L=32, 16, H=128, W=128] fp32
// Output = images after 5 doubling pscan steps (step = 1,2,4,8,16).

constexpr int B  = 4;
constexpr int L  = 32;
constexpr int C  = 16;
constexpr int H  = 128;
constexpr int W  = 128;
constexpr int HW = H * W;
constexpr int FSTR = 2 * HW;   // floats per (b,t) in flows
constexpr int ISTR = C * HW;   // floats per (b,t) in images
constexpr int NPIX = B * L * HW;

// Allocation-free scratch (module-load-time device globals).
__device__ float g_flowsA[B * L * 2 * HW];   // 16 MiB
__device__ float g_flowsB[B * L * 2 * HW];   // 16 MiB
__device__ float g_imagesA[B * L * C * HW];  // 128 MiB

__global__ __launch_bounds__(256)
void pscan_step_kernel(const float* __restrict__ sf,   // src flows  [B,L,2,H,W]
                       const float* __restrict__ si,   // src images [B,L,C,H,W]
                       float* __restrict__ df,         // dst flows
                       float* __restrict__ di,         // dst images
                       int step)
{
    int idx = blockIdx.x * blockDim.x + threadIdx.x;
    if (idx >= NPIX) return;

    int hw = idx % HW;
    int bt = idx / HW;          // b*L + t
    int t  = bt % L;
    int w  = hw % W;
    int h  = hw / W;

    const float* fcur = sf + (size_t)bt * FSTR + hw;
    const float* icur = si + (size_t)bt * ISTR + hw;
    float*       fo   = df + (size_t)bt * FSTR + hw;
    float*       io   = di + (size_t)bt * ISTR + hw;

    if (t < step) {
        // passthrough copy (fully coalesced)
        fo[0]  = fcur[0];
        fo[HW] = fcur[HW];
        #pragma unroll
        for (int c = 0; c < C; c++) io[c * HW] = icur[c * HW];
        return;
    }

    // --- build sample grid from current flow ---
    float fxv = fcur[0];
    float fyv = fcur[HW];
    float gx = ((float)w + 0.5f) * (2.0f / W) - 1.0f + fxv;
    float gy = ((float)h + 0.5f) * (2.0f / H) - 1.0f + fyv;

    // wrap x: remainder(gx+1, 2) - 1  (python-style mod, result in [0,2))
    float r = fmodf(gx + 1.0f, 2.0f);
    if (r < 0.0f) r += 2.0f;
    float gxw = r - 1.0f;

    // unnormalize (align_corners=False)
    float x = (gxw + 1.0f) * (0.5f * W) - 0.5f;
    float y = (gy  + 1.0f) * (0.5f * H) - 0.5f;

    float x0f = floorf(x);
    float y0f = floorf(y);
    float wx = x - x0f;
    float wy = y - y0f;
    int x0 = (int)x0f, y0 = (int)y0f;
    int x1 = x0 + 1,   y1 = y0 + 1;

    int x0c = min(max(x0, 0), W - 1);
    int x1c = min(max(x1, 0), W - 1);
    int y0c = min(max(y0, 0), H - 1);
    int y1c = min(max(y1, 0), H - 1);

    float w00 = (1.0f - wx) * (1.0f - wy);
    float w01 = wx * (1.0f - wy);
    float w10 = (1.0f - wx) * wy;
    float w11 = wx * wy;

    int o00 = y0c * W + x0c;
    int o01 = y0c * W + x1c;
    int o10 = y1c * W + x0c;
    int o11 = y1c * W + x1c;

    // --- flows: border padding (clamped indices, full weights) ---
    const float* fprev = sf + (size_t)(bt - step) * FSTR;
    #pragma unroll
    for (int c = 0; c < 2; c++) {
        const float* p = fprev + c * HW;
        float v = w00 * p[o00] + w01 * p[o01] + w10 * p[o10] + w11 * p[o11];
        fo[c * HW] = fcur[c * HW] + v;
    }

    // --- images: zeros padding (zero out-of-bounds taps) ---
    bool vx0 = (x0 >= 0) && (x0 < W);
    bool vx1 = (x1 >= 0) && (x1 < W);
    bool vy0 = (y0 >= 0) && (y0 < H);
    bool vy1 = (y1 >= 0) && (y1 < H);
    float z00 = (vy0 && vx0) ? w00 : 0.0f;
    float z01 = (vy0 && vx1) ? w01 : 0.0f;
    float z10 = (vy1 && vx0) ? w10 : 0.0f;
    float z11 = (vy1 && vx1) ? w11 : 0.0f;

    const float* iprev = si + (size_t)(bt - step) * ISTR;
    #pragma unroll
    for (int c = 0; c < C; c++) {
        const float* p = iprev + c * HW;
        float v = z00 * p[o00] + z01 * p[o01] + z10 * p[o10] + z11 * p[o11];
        io[c * HW] = icur[c * HW] + v;
    }
}

extern "C" void kernel_launch(void* const* d_in, const int* in_sizes, int n_in,
                              void* d_out, int out_size)
{
    // metadata order: flows first, images second; guard by size just in case.
    const float* flows  = (const float*)d_in[0];
    const float* images = (const float*)d_in[1];
    if (n_in >= 2 && in_sizes[0] > in_sizes[1]) {
        flows  = (const float*)d_in[1];
        images = (const float*)d_in[0];
    }
    float* out = (float*)d_out;

    float *fA, *fB, *iA;
    cudaGetSymbolAddress((void**)&fA, g_flowsA);
    cudaGetSymbolAddress((void**)&fB, g_flowsB);
    cudaGetSymbolAddress((void**)&iA, g_imagesA);

    const int threads = 256;
    const int blocks  = (NPIX + threads - 1) / threads;

    // 5 steps, odd count: start d_in -> d_out, ping-pong d_out <-> scratch,
    // so the final step lands images in d_out.
    pscan_step_kernel<<<blocks, threads>>>(flows, images, fA, out, 1);
    pscan_step_kernel<<<blocks, threads>>>(fA, out,      fB, iA,  2);
    pscan_step_kernel<<<blocks, threads>>>(fB, iA,       fA, out, 4);
    pscan_step_kernel<<<blocks, threads>>>(fA, out,      fB, iA,  8);
    pscan_step_kernel<<<blocks, threads>>>(fB, iA,       fA, out, 16);
}